// round 12
// baseline (speedup 1.0000x reference)
#include <cuda_runtime.h>
#include <cuda_fp16.h>

// PPISP pipeline. Round 12 = R11 pipelining + 2-point vectorized streaming.
//  - 2 points/thread, all streaming I/O as float2/int2 (halves streaming
//    instruction count vs R11's scalar), distance-1 register pipeline.
//  - frame record 24B mixed: s_q {m00,m11,m22,h2(m01,m02)} + s_u 8B
//  - camera: s_Pa[j*4+c] = {h2(v0,v1), h2(p2,p3), h2(p4,mhd), a},
//    s_HC[c] = {h2(hc,hb) x3};  mhd = -d*0.5/c, hc = 0.5/c, hb = 0.5*b
//  - out = hb + hb*tanh(fma(xp, hc, mhd)),  xp = ex2(a*lg2(max(y,1e-6)))
//  launch_bounds(256,4): 64-reg cap, 32 warps/SM.

#define MAX_F 4096

__device__ float4 g_q[MAX_F];
__device__ uint2  g_u[MAX_F];
__device__ __align__(128) float4 g_Pa[3 * 4];   // [j][c]
__device__ __align__(64)  float4 g_HC[4];

__device__ __forceinline__ unsigned int f2h2(float a, float b) {
    __half2 h = __floats2half2_rn(a, b);
    return *reinterpret_cast<unsigned int*>(&h);
}
__device__ __forceinline__ float2 h22f2(unsigned int u) {
    __half2 h = *reinterpret_cast<__half2*>(&u);
    return __half22float2(h);
}

__global__ void ppisp_precompute(const float* __restrict__ expo,
                                 const float* __restrict__ vig,
                                 const float* __restrict__ colp,
                                 const float* __restrict__ crf,
                                 int F, int C)
{
    int t = blockIdx.x * blockDim.x + threadIdx.x;
    if (t < F) {
        float e  = exp2f(expo[t]);
        const float* cp = colp + t * 8;
        float s0 = e * expf(cp[0]);
        float s1 = e;
        float s2 = e * expf(cp[1]);
        float o0 = cp[2], o1 = cp[3], o2 = cp[4];
        float o3 = cp[5], o4 = cp[6], o5 = cp[7];
        float m00 = (1.0f - o0 - o1) * s0, m01 = o0 * s1, m02 = o1 * s2;
        float m10 = o2 * s0, m11 = (1.0f - o2 - o3) * s1, m12 = o3 * s2;
        float m20 = o4 * s0, m21 = o5 * s1, m22 = (1.0f - o4 - o5) * s2;
        float4 q;
        q.x = m00; q.y = m11; q.z = m22;
        q.w = __uint_as_float(f2h2(m01, m02));
        g_q[t] = q;
        g_u[t] = make_uint2(f2h2(m10, m12), f2h2(m20, m21));
    }
    if (blockIdx.x == 0 && (int)threadIdx.x < C * 3 && (int)threadIdx.x < 12) {
        int c = threadIdx.x / 3;
        int j = threadIdx.x % 3;
        const float* vp = vig + c * 15 + j * 5;
        const float* kp = crf + c * 12 + j * 4;
        float a  = log1pf(expf(kp[0])) + 0.3f;   // accurate softplus (once)
        float cc = log1pf(expf(kp[2])) + 0.1f;
        float d  = kp[3];
        float hc  = 0.5f / cc;
        float mhd = -d * hc;
        float4 P;
        P.x = __uint_as_float(f2h2(vp[0], vp[1]));
        P.y = __uint_as_float(f2h2(vp[2], vp[3]));
        P.z = __uint_as_float(f2h2(vp[4], mhd));
        P.w = a;
        g_Pa[j * 4 + c] = P;
    }
    if (blockIdx.x == 0 && (int)threadIdx.x < C && (int)threadIdx.x < 4) {
        int c = threadIdx.x;
        const float* kp = crf + c * 12;
        float4 H; float* Hf = (float*)&H;
#pragma unroll
        for (int j = 0; j < 3; j++) {
            float b  = log1pf(expf(kp[4 * j + 1])) + 0.3f;
            float cc = log1pf(expf(kp[4 * j + 2])) + 0.1f;
            Hf[j] = __uint_as_float(f2h2(0.5f / cc, 0.5f * b));
        }
        Hf[3] = 0.0f;
        g_HC[c] = H;
    }
}

__device__ __forceinline__ float fast_lg2(float x) {
    float y; asm("lg2.approx.f32 %0, %1;" : "=f"(y) : "f"(x)); return y;
}
__device__ __forceinline__ float fast_ex2(float x) {
    float y; asm("ex2.approx.f32 %0, %1;" : "=f"(y) : "f"(x)); return y;
}
__device__ __forceinline__ float fast_tanh(float x) {
    float y; asm("tanh.approx.f32 %0, %1;" : "=f"(y) : "f"(x)); return y;
}

struct Pt2 {
    float2 r01, r23, r45;   // 6 rgb floats for 2 points
    float2 pa, pb;          // 4 coord floats
    int2 c2, f2;
};

__device__ __forceinline__ Pt2 load_pt2(const float2* __restrict__ rgb2,
                                        const float2* __restrict__ pc2,
                                        const int2* __restrict__ cam2,
                                        const int2* __restrict__ frm2,
                                        int t)
{
    Pt2 p;
    p.r01 = __ldcs(rgb2 + 3 * t + 0);
    p.r23 = __ldcs(rgb2 + 3 * t + 1);
    p.r45 = __ldcs(rgb2 + 3 * t + 2);
    p.pa  = __ldcs(pc2 + 2 * t + 0);
    p.pb  = __ldcs(pc2 + 2 * t + 1);
    p.c2  = __ldcs(cam2 + t);
    p.f2  = __ldcs(frm2 + t);
    return p;
}

__device__ __forceinline__ void compute_point(
    float r, float g, float b, float px, float py, int c, int f,
    float invW2, float invH2,
    const float4* __restrict__ s_q, const uint2* __restrict__ s_u,
    const float4* __restrict__ s_Pa, const float4* __restrict__ s_HC,
    float* __restrict__ o)
{
    float u = fmaf(px, invW2, -1.0f);
    float v = fmaf(py, invH2, -1.0f);

    float rgbv[3] = {r, g, b};
    float t[3], aj[3], mhdj[3];
#pragma unroll
    for (int j = 0; j < 3; j++) {
        float4 P = s_Pa[j * 4 + c];
        float2 v01 = h22f2(__float_as_uint(P.x));
        float2 p23 = h22f2(__float_as_uint(P.y));
        float2 p4m = h22f2(__float_as_uint(P.z));
        float du = u - v01.x;
        float dv = v - v01.y;
        float r2 = fmaf(du, du, dv * dv);
        float gnv = fmaf(r2, fmaf(r2, fmaf(r2, p4m.x, p23.y), p23.x), 1.0f);
        t[j]    = rgbv[j] * gnv;
        aj[j]   = P.w;
        mhdj[j] = p4m.y;
    }

    float4 q  = s_q[f];
    uint2  uo = s_u[f];
    float2 m0102 = h22f2(__float_as_uint(q.w));
    float2 m1012 = h22f2(uo.x);
    float2 m2021 = h22f2(uo.y);

    float y0 = fmaf(q.x,     t[0], fmaf(m0102.x, t[1], m0102.y * t[2]));
    float y1 = fmaf(m1012.x, t[0], fmaf(q.y,     t[1], m1012.y * t[2]));
    float y2 = fmaf(m2021.x, t[0], fmaf(m2021.y, t[1], q.z     * t[2]));
    float yv[3] = {y0, y1, y2};

    float4 HC = s_HC[c];
    const float* Hf = (const float*)&HC;
#pragma unroll
    for (int j = 0; j < 3; j++) {
        float2 hcb = h22f2(__float_as_uint(Hf[j]));
        float xp  = fast_ex2(aj[j] * fast_lg2(fmaxf(yv[j], 1e-6f)));
        float arg = fmaf(xp, hcb.x, mhdj[j]);
        o[j] = fmaf(hcb.y, fast_tanh(arg), hcb.y);
    }
}

__global__ void __launch_bounds__(256, 4)
ppisp_main(const float* __restrict__ rgb,
           const float* __restrict__ coords,
           const int*   __restrict__ cam,
           const int*   __restrict__ frm,
           const int*   __restrict__ pW,
           const int*   __restrict__ pH,
           float* __restrict__ out,
           int B, int F)
{
    extern __shared__ float4 smbase[];
    float4* s_q  = smbase;                  // [F] 16B
    float4* s_Pa = s_q + F;                 // [12]
    float4* s_HC = s_Pa + 12;               // [4]
    uint2*  s_u  = (uint2*)(s_HC + 4);      // [F] 8B

    for (int i = threadIdx.x; i < F; i += blockDim.x) {
        s_q[i] = g_q[i];
        s_u[i] = g_u[i];
    }
    if (threadIdx.x < 12) s_Pa[threadIdx.x] = g_Pa[threadIdx.x];
    if (threadIdx.x < 4)  s_HC[threadIdx.x] = g_HC[threadIdx.x];
    __syncthreads();

    float invW2 = 2.0f / (float)__ldg(pW);
    float invH2 = 2.0f / (float)__ldg(pH);

    const float2* rgb2 = (const float2*)rgb;
    const float2* pc2  = (const float2*)coords;
    const int2*   cam2 = (const int2*)cam;
    const int2*   frm2 = (const int2*)frm;

    int stride = gridDim.x * blockDim.x;
    int gid = blockIdx.x * blockDim.x + threadIdx.x;
    int nP = B >> 1;   // full pairs

    if (gid < nP) {
        int t = gid;
        Pt2 a = load_pt2(rgb2, pc2, cam2, frm2, t);

        while (true) {
            int tn = t + stride;
            bool hn = (tn < nP);
            Pt2 nb;
            if (hn) nb = load_pt2(rgb2, pc2, cam2, frm2, tn);

            float o[6];
            compute_point(a.r01.x, a.r01.y, a.r23.x, a.pa.x, a.pa.y,
                          a.c2.x, a.f2.x, invW2, invH2,
                          s_q, s_u, s_Pa, s_HC, o + 0);
            compute_point(a.r23.y, a.r45.x, a.r45.y, a.pb.x, a.pb.y,
                          a.c2.y, a.f2.y, invW2, invH2,
                          s_q, s_u, s_Pa, s_HC, o + 3);

            float2* O = (float2*)out;
            __stcs(O + 3 * t + 0, make_float2(o[0], o[1]));
            __stcs(O + 3 * t + 1, make_float2(o[2], o[3]));
            __stcs(O + 3 * t + 2, make_float2(o[4], o[5]));

            if (!hn) break;
            a = nb;
            t = tn;
        }
    }

    // odd tail point (at most one in the whole grid)
    if (gid == 0 && (B & 1)) {
        int i = B - 1;
        float o[3];
        compute_point(rgb[3 * i], rgb[3 * i + 1], rgb[3 * i + 2],
                      coords[2 * i], coords[2 * i + 1],
                      cam[i], frm[i], invW2, invH2,
                      s_q, s_u, s_Pa, s_HC, o);
        out[3 * i + 0] = o[0];
        out[3 * i + 1] = o[1];
        out[3 * i + 2] = o[2];
    }
}

extern "C" void kernel_launch(void* const* d_in, const int* in_sizes, int n_in,
                              void* d_out, int out_size) {
    const float* expo   = (const float*)d_in[0];
    const float* vig    = (const float*)d_in[1];
    const float* colp   = (const float*)d_in[2];
    const float* crf    = (const float*)d_in[3];
    const float* rgb    = (const float*)d_in[4];
    const float* coords = (const float*)d_in[5];
    const int*   cam    = (const int*)d_in[6];
    const int*   frm    = (const int*)d_in[7];
    const int*   pW     = (const int*)d_in[8];
    const int*   pH     = (const int*)d_in[9];
    float* out = (float*)d_out;

    int F = in_sizes[0];
    int C = in_sizes[1] / 15;
    int B = in_sizes[6];
    if (F > MAX_F) F = MAX_F;   // table capacity guard (problem uses F=1000)

    // s_q[F] + s_Pa[12] + s_HC[4] + s_u[F]
    size_t shmem = (size_t)F * 16 + 16 * 16 + (size_t)F * 8;

    {
        int pthreads = 256;
        int pwork = (F > C * 3) ? F : C * 3;
        int pblocks = (pwork + pthreads - 1) / pthreads;
        ppisp_precompute<<<pblocks, pthreads>>>(expo, vig, colp, crf, F, C);
    }

    static bool attr_done = false;
    if (!attr_done) {
        cudaFuncSetAttribute(ppisp_main,
                             cudaFuncAttributeMaxDynamicSharedMemorySize,
                             (int)shmem > 49152 ? (int)shmem : 49152);
        attr_done = true;
    }

    int nP = B / 2;
    int blocks = (nP + 255) / 256;
    if (blocks < 1) blocks = 1;
    int maxb = 148 * 4;
    if (blocks > maxb) blocks = maxb;
    ppisp_main<<<blocks, 256, shmem>>>(rgb, coords, cam, frm, pW, pH,
                                       out, B, F);
}